// round 6
// baseline (speedup 1.0000x reference)
#include <cuda_runtime.h>

#define N_NEURON 500000
#define N_EDGE   10000000

// dual-exponential constants (match reference exactly)
#define DT_C     0.1f
#define LAMDA_D  (0.1f / 2.0f)    // DT/TAO_D
#define LAMDA_R  (0.1f / 10.0f)   // DT/TAO_R
#define INV_TAO_D 0.5f            // 1/TAO_D

// scratch: r_new lives here between the two kernels (no cudaMalloc allowed)
__device__ float g_rnew[N_NEURON];

// ---------------------------------------------------------------------------
// Kernel A: per-neuron fused update, float4-vectorized (N_NEURON % 4 == 0).
// 128-thread blocks: 977 blocks over 148 SMs (6.6/SM) cuts the single-wave
// load-imbalance tail vs 256-thread blocks (488 blocks, 3.3/SM -> 33% skew).
//   Iback_new = Iback + dt_over_tau*(noise - Iback)
//   Ieff      = Iback_new / sqrt_coeff * sig + mu
//   s_new     = s + LAMDA_R*(-s + spike/TAO_D)
//   r_new     = r - LAMDA_D*r + DT*s_new
// Writes r_new to scratch, seeds out = Ieff (accumulator base).
// ---------------------------------------------------------------------------
__global__ void __launch_bounds__(128) neuron_kernel(
                              const float4* __restrict__ Iback,
                              const float4* __restrict__ spike,
                              const float4* __restrict__ s,
                              const float4* __restrict__ r,
                              const float4* __restrict__ noise,
                              const float* __restrict__ dt_over_tau,
                              const float* __restrict__ sqrt_coeff,
                              const float* __restrict__ sig,
                              const float* __restrict__ mu,
                              float4* __restrict__ out)
{
    int i = blockIdx.x * blockDim.x + threadIdx.x;
    if (i >= N_NEURON / 4) return;

    float dtau  = __ldg(dt_over_tau);
    float scale = __ldg(sig) / __ldg(sqrt_coeff);
    float m     = __ldg(mu);

    float4 ib = Iback[i];
    float4 nz = noise[i];
    float4 sv = s[i];
    float4 sp = spike[i];
    float4 rv = r[i];

    float4 ieff, rn;
    {
        float ibn = ib.x + dtau * (nz.x - ib.x);
        ieff.x = ibn * scale + m;
        float sn = sv.x + LAMDA_R * (-sv.x + sp.x * INV_TAO_D);
        rn.x = rv.x - LAMDA_D * rv.x + DT_C * sn;
    }
    {
        float ibn = ib.y + dtau * (nz.y - ib.y);
        ieff.y = ibn * scale + m;
        float sn = sv.y + LAMDA_R * (-sv.y + sp.y * INV_TAO_D);
        rn.y = rv.y - LAMDA_D * rv.y + DT_C * sn;
    }
    {
        float ibn = ib.z + dtau * (nz.z - ib.z);
        ieff.z = ibn * scale + m;
        float sn = sv.z + LAMDA_R * (-sv.z + sp.z * INV_TAO_D);
        rn.z = rv.z - LAMDA_D * rv.z + DT_C * sn;
    }
    {
        float ibn = ib.w + dtau * (nz.w - ib.w);
        ieff.w = ibn * scale + m;
        float sn = sv.w + LAMDA_R * (-sv.w + sp.w * INV_TAO_D);
        rn.w = rv.w - LAMDA_D * rv.w + DT_C * sn;
    }

    reinterpret_cast<float4*>(g_rnew)[i] = rn;
    out[i] = ieff;   // accumulator base (out is poisoned by harness)
}

// ---------------------------------------------------------------------------
// Kernel B: COO edge scatter, 4 edges per thread (best measured config:
// 76.4us @ L2=90.4%; kernel is LTS-traffic-bound at ~760 MB of sectors).
//   out[post_e] += w_e * r_new[pre_e]
// edges are INT32 on device: post = edges[0:N_EDGE], pre = edges[N_EDGE:2N].
// Gathers issued before atomics; r_new (2 MB) and out (2 MB) are
// L2-resident; atomics compile to REDG.
// ---------------------------------------------------------------------------
__global__ void __launch_bounds__(256) edge_kernel(
                            const int* __restrict__ post,
                            const int* __restrict__ pre,
                            const float* __restrict__ w,
                            float* __restrict__ out)
{
    int t = blockIdx.x * blockDim.x + threadIdx.x;
    int i = t * 4;
    if (i >= N_EDGE) return;   // N_EDGE % 4 == 0, full quads only

    int4   p  = *reinterpret_cast<const int4*>(post + i);
    int4   q  = *reinterpret_cast<const int4*>(pre + i);
    float4 ww = *reinterpret_cast<const float4*>(w + i);

    // gather first (maximize MLP), then scatter
    float r0 = __ldg(&g_rnew[q.x]);
    float r1 = __ldg(&g_rnew[q.y]);
    float r2 = __ldg(&g_rnew[q.z]);
    float r3 = __ldg(&g_rnew[q.w]);

    atomicAdd(out + p.x, ww.x * r0);
    atomicAdd(out + p.y, ww.y * r1);
    atomicAdd(out + p.z, ww.z * r2);
    atomicAdd(out + p.w, ww.w * r3);
}

extern "C" void kernel_launch(void* const* d_in, const int* in_sizes, int n_in,
                              void* d_out, int out_size)
{
    const float* weight      = (const float*)d_in[0];
    const int*   edges       = (const int*)d_in[1];   // [2, N_EDGE] int32
    const float* Iback       = (const float*)d_in[2];
    const float* spike       = (const float*)d_in[3];
    const float* s           = (const float*)d_in[4];
    const float* r           = (const float*)d_in[5];
    const float* noise       = (const float*)d_in[6];
    const float* dt_over_tau = (const float*)d_in[7];
    const float* sqrt_coeff  = (const float*)d_in[8];
    const float* sig         = (const float*)d_in[9];
    const float* mu          = (const float*)d_in[10];
    float* out = (float*)d_out;

    const int* post = edges;
    const int* pre  = edges + N_EDGE;

    int nvec = N_NEURON / 4;
    int nthreads_a = 128;
    int nblocks = (nvec + nthreads_a - 1) / nthreads_a;
    neuron_kernel<<<nblocks, nthreads_a>>>(
        (const float4*)Iback, (const float4*)spike, (const float4*)s,
        (const float4*)r, (const float4*)noise,
        dt_over_tau, sqrt_coeff, sig, mu, (float4*)out);

    int threads = 256;
    int nthreads_edge = N_EDGE / 4;
    int eblocks = (nthreads_edge + threads - 1) / threads;
    edge_kernel<<<eblocks, threads>>>(post, pre, weight, out);
}